// round 5
// baseline (speedup 1.0000x reference)
#include <cuda_runtime.h>
#include <cuda_bf16.h>

#define B_  2
#define L_  2048
#define D_  1024
#define H_  16
#define DH_ 64

// Scratch: Q,K transposed per (b,h): [(bh*64 + d)][l]; V natural: [(bh*L + l)][d]
__device__ float g_Qt[B_ * H_ * DH_ * L_];
__device__ float g_Kt[B_ * H_ * DH_ * L_];
__device__ float g_V [B_ * H_ * L_ * DH_];

// ---------------------------------------------------------------------------
// Fused QKV projection: C[e][n] = sum_d W[e][d] * x[n][d]
// e in [0,3072): 0-1023 -> Q, 1024-2047 -> K, 2048-3071 -> V
// 128x128 tile, BK=8, 256 threads, 8x8 per thread, register double-buffer.
// ---------------------------------------------------------------------------
__global__ __launch_bounds__(256, 2)
void qkv_gemm_kernel(const float* __restrict__ x,
                     const float* __restrict__ Wq,
                     const float* __restrict__ Wk,
                     const float* __restrict__ Wv)
{
    __shared__ float As[8][128];
    __shared__ float Bs[8][128];

    const int n0  = blockIdx.x * 128;          // rows of x (b*L + l)
    const int eg0 = blockIdx.y * 128;          // global output feature tile
    const int which = eg0 >> 10;               // 0=Q,1=K,2=V
    const int e0 = eg0 & 1023;                 // feature offset within weight
    const float* __restrict__ W = (which == 0) ? Wq : (which == 1) ? Wk : Wv;

    const int tid = threadIdx.x;
    const int tx = tid & 15;
    const int ty = tid >> 4;

    const int lr = tid >> 1;                   // 0..127 (row within tile)
    const int lc = (tid & 1) << 2;             // 0 or 4 (k offset)

    const float* Ap = W + (e0 + lr) * D_ + lc;
    const float* Bp = x + (n0 + lr) * D_ + lc;

    float4 ra = *(const float4*)Ap;
    float4 rb = *(const float4*)Bp;

    float acc[8][8];
#pragma unroll
    for (int i = 0; i < 8; i++)
#pragma unroll
        for (int j = 0; j < 8; j++) acc[i][j] = 0.0f;

    for (int d0 = 0; d0 < D_; d0 += 8) {
        __syncthreads();
        As[lc + 0][lr] = ra.x; As[lc + 1][lr] = ra.y;
        As[lc + 2][lr] = ra.z; As[lc + 3][lr] = ra.w;
        Bs[lc + 0][lr] = rb.x; Bs[lc + 1][lr] = rb.y;
        Bs[lc + 2][lr] = rb.z; Bs[lc + 3][lr] = rb.w;
        __syncthreads();

        if (d0 + 8 < D_) {                     // register prefetch next chunk
            ra = *(const float4*)(Ap + d0 + 8);
            rb = *(const float4*)(Bp + d0 + 8);
        }

#pragma unroll
        for (int kk = 0; kk < 8; kk++) {
            float4 a0 = *(const float4*)&As[kk][ty * 4];
            float4 a1 = *(const float4*)&As[kk][ty * 4 + 64];
            float4 b0 = *(const float4*)&Bs[kk][tx * 4];
            float4 b1 = *(const float4*)&Bs[kk][tx * 4 + 64];
            float av[8] = {a0.x, a0.y, a0.z, a0.w, a1.x, a1.y, a1.z, a1.w};
            float bv[8] = {b0.x, b0.y, b0.z, b0.w, b1.x, b1.y, b1.z, b1.w};
#pragma unroll
            for (int i = 0; i < 8; i++)
#pragma unroll
                for (int j = 0; j < 8; j++)
                    acc[i][j] = fmaf(av[i], bv[j], acc[i][j]);
        }
    }

    const int b  = n0 >> 11;                   // n tile never crosses batch
    const int l0 = n0 & (L_ - 1);

#pragma unroll
    for (int i = 0; i < 8; i++) {
        const int row = (i < 4) ? (ty * 4 + i) : (64 + ty * 4 + (i - 4));
        const int el = e0 + row;               // 0..1023 within this weight
        float4 v0 = make_float4(acc[i][0], acc[i][1], acc[i][2], acc[i][3]);
        float4 v1 = make_float4(acc[i][4], acc[i][5], acc[i][6], acc[i][7]);
        if (which == 0) {
            float* base = g_Qt + (size_t)(b * 1024 + el) * L_ + l0;
            *(float4*)(base + tx * 4)      = v0;
            *(float4*)(base + 64 + tx * 4) = v1;
        } else if (which == 1) {
            float* base = g_Kt + (size_t)(b * 1024 + el) * L_ + l0;
            *(float4*)(base + tx * 4)      = v0;
            *(float4*)(base + 64 + tx * 4) = v1;
        } else {
            const int hh = el >> 6, dh = el & 63;
            float* vb = g_V + (size_t)(b * H_ + hh) * L_ * DH_ + dh;
#pragma unroll
            for (int j = 0; j < 8; j++) {
                const int col = (j < 4) ? (tx * 4 + j) : (64 + tx * 4 + (j - 4));
                vb[(size_t)(l0 + col) * DH_] = acc[i][j];
            }
        }
    }
}

// ---------------------------------------------------------------------------
// Flash attention, fp32, causal + padding mask, tau*tanh logit cap.
// Key identity: exp(30*tanh(s) - 30) = exp(-60 / (exp(2s)+1))  (exact),
// and since logits <= 30, a FIXED shift of 30 replaces the online max.
// One CTA = 64 q-rows of one (b,h). 256 threads, 4x4 micro-tile.
// ---------------------------------------------------------------------------
__global__ __launch_bounds__(256)
void attn_kernel(const int* __restrict__ mask, float* __restrict__ out)
{
    __shared__ float Qs [64 * 64];   // [d][i]
    __shared__ float KPs[64 * 64];   // K as [d][j], then P as [i][j]
    __shared__ float Vs [64 * 64];   // [j][d]

    const int qt = blockIdx.x;       // q tile 0..31
    const int bh = blockIdx.y;       // 0..31
    const int b  = bh >> 4;
    const int h  = bh & 15;
    const int q0 = qt * 64;

    const int tid = threadIdx.x;
    const int tx = tid & 15;
    const int ty = tid >> 4;
    const int i0 = ty * 4;           // q rows
    const int c0 = tx * 4;           // key cols (scores) / dh cols (output)

    const float* qsrc = g_Qt + (size_t)(bh * 64) * L_ + q0;
#pragma unroll
    for (int k = 0; k < 4; k++) {    // load Q tile [d][i], coalesced, no conflicts
        int idx4 = tid + k * 256;    // 0..1023 float4s
        int d = idx4 >> 4;
        int i = (idx4 & 15) << 2;
        *(float4*)&Qs[d * 64 + i] = *(const float4*)(qsrc + (size_t)d * L_ + i);
    }

    float acc[4][4];
    float den[4] = {0.f, 0.f, 0.f, 0.f};
#pragma unroll
    for (int r = 0; r < 4; r++)
#pragma unroll
        for (int c = 0; c < 4; c++) acc[r][c] = 0.0f;

    const float* ksrc = g_Kt + (size_t)(bh * 64) * L_;
    const float* vsrc_base = g_V + (size_t)bh * L_ * DH_;
    const int*   mrow = mask + b * L_;

    for (int kt = 0; kt <= qt; kt++) {
        const int k0 = kt * 64;
        __syncthreads();             // prior PV done with KPs/Vs
#pragma unroll
        for (int k = 0; k < 4; k++) {
            int idx4 = tid + k * 256;
            int d = idx4 >> 4;
            int j = (idx4 & 15) << 2;
            *(float4*)&KPs[d * 64 + j] =
                *(const float4*)(ksrc + (size_t)d * L_ + k0 + j);
        }
        const float* vsrc = vsrc_base + (size_t)k0 * DH_;   // contiguous 16KB
#pragma unroll
        for (int k = 0; k < 4; k++) {
            int idx4 = tid + k * 256;
            *(float4*)&Vs[idx4 * 4] = *(const float4*)(vsrc + idx4 * 4);
        }
        __syncthreads();

        // S = Q K^T over d (both operands [d][*] -> broadcast + stride-free LDS)
        float s[4][4];
#pragma unroll
        for (int r = 0; r < 4; r++)
#pragma unroll
            for (int c = 0; c < 4; c++) s[r][c] = 0.0f;
#pragma unroll 8
        for (int d = 0; d < 64; d++) {
            float4 qa = *(const float4*)&Qs[d * 64 + i0];
            float4 kb = *(const float4*)&KPs[d * 64 + c0];
            float av[4] = {qa.x, qa.y, qa.z, qa.w};
            float bv[4] = {kb.x, kb.y, kb.z, kb.w};
#pragma unroll
            for (int r = 0; r < 4; r++)
#pragma unroll
                for (int c = 0; c < 4; c++)
                    s[r][c] = fmaf(av[r], bv[c], s[r][c]);
        }

        int mk[4];
#pragma unroll
        for (int c = 0; c < 4; c++) mk[c] = __ldg(mrow + k0 + c0 + c);

        float p[4][4];
#pragma unroll
        for (int r = 0; r < 4; r++) {
#pragma unroll
            for (int c = 0; c < 4; c++) {
                float sv = s[r][c] * 0.125f;                 // 1/sqrt(Dh)
                float t  = __expf(2.0f * sv);
                float pv = __expf(__fdividef(-60.0f, t + 1.0f));
                bool keep = (mk[c] != 0) &&
                            ((kt < qt) || ((c0 + c) <= (i0 + r)));
                pv = keep ? pv : 0.0f;
                p[r][c] = pv;
                den[r] += pv;
            }
        }
        __syncthreads();             // all done reading KPs as K
#pragma unroll
        for (int r = 0; r < 4; r++)  // P tile, natural [i][j], STS.128 conflict-free
            *(float4*)&KPs[(i0 + r) * 64 + c0] =
                make_float4(p[r][0], p[r][1], p[r][2], p[r][3]);
        __syncthreads();

        // O += P V : k-dim = j, pa rows broadcast, vb rows conflict-free
#pragma unroll 4
        for (int jj = 0; jj < 64; jj += 4) {
            float4 pa[4];
#pragma unroll
            for (int r = 0; r < 4; r++)
                pa[r] = *(const float4*)&KPs[(i0 + r) * 64 + jj];
            float4 vb[4];
#pragma unroll
            for (int u = 0; u < 4; u++)
                vb[u] = *(const float4*)&Vs[(jj + u) * 64 + c0];
#pragma unroll
            for (int r = 0; r < 4; r++) {
                float pr[4] = {pa[r].x, pa[r].y, pa[r].z, pa[r].w};
#pragma unroll
                for (int u = 0; u < 4; u++) {
                    acc[r][0] = fmaf(pr[u], vb[u].x, acc[r][0]);
                    acc[r][1] = fmaf(pr[u], vb[u].y, acc[r][1]);
                    acc[r][2] = fmaf(pr[u], vb[u].z, acc[r][2]);
                    acc[r][3] = fmaf(pr[u], vb[u].w, acc[r][3]);
                }
            }
        }
    }

    // row-sum reduce across the 16-lane tx group (stays inside warp halves)
#pragma unroll
    for (int r = 0; r < 4; r++) {
#pragma unroll
        for (int off = 8; off > 0; off >>= 1)
            den[r] += __shfl_xor_sync(0xffffffffu, den[r], off);
    }

#pragma unroll
    for (int r = 0; r < 4; r++) {
        float inv = __frcp_rn(den[r]);   // den > 0: diagonal always kept
        float4 o = make_float4(acc[r][0] * inv, acc[r][1] * inv,
                               acc[r][2] * inv, acc[r][3] * inv);
        *(float4*)&out[(size_t)(b * L_ + q0 + i0 + r) * (H_ * DH_) + h * DH_ + c0] = o;
    }
}

// ---------------------------------------------------------------------------
extern "C" void kernel_launch(void* const* d_in, const int* in_sizes, int n_in,
                              void* d_out, int out_size)
{
    const float* x    = (const float*)d_in[0];
    const int*   mask = (const int*)  d_in[1];
    const float* Wq   = (const float*)d_in[2];
    const float* Wk   = (const float*)d_in[3];
    const float* Wv   = (const float*)d_in[4];
    float* out = (float*)d_out;

    qkv_gemm_kernel<<<dim3(32, 24), 256>>>(x, Wq, Wk, Wv);
    attn_kernel<<<dim3(32, 32), 256>>>(mask, out);
}

// round 6
// speedup vs baseline: 1.0353x; 1.0353x over previous
#include <cuda_runtime.h>
#include <cuda_bf16.h>

#define B_  2
#define L_  2048
#define D_  1024
#define H_  16
#define DH_ 64

typedef unsigned long long u64;

// ---- packed f32x2 helpers (sm_103a FFMA2 path; IEEE-exact per lane) ----
__device__ __forceinline__ u64 pk2(float lo, float hi) {
    u64 r; asm("mov.b64 %0,{%1,%2};" : "=l"(r) : "f"(lo), "f"(hi)); return r;
}
__device__ __forceinline__ u64 dup2(float v) { return pk2(v, v); }
__device__ __forceinline__ u64 ffma2(u64 a, u64 b, u64 c) {
    u64 d; asm("fma.rn.f32x2 %0,%1,%2,%3;" : "=l"(d) : "l"(a), "l"(b), "l"(c));
    return d;
}
__device__ __forceinline__ float2 upk2(u64 v) {
    float lo, hi; asm("mov.b64 {%0,%1},%2;" : "=f"(lo), "=f"(hi) : "l"(v));
    return make_float2(lo, hi);
}

// Scratch: Q,K transposed per (b,h): [(bh*64 + d)][l]; V natural: [(bh*L + l)][d]
__device__ float g_Qt[B_ * H_ * DH_ * L_];
__device__ float g_Kt[B_ * H_ * DH_ * L_];
__device__ float g_V [B_ * H_ * L_ * DH_];

// ---------------------------------------------------------------------------
// Fused QKV projection: C[e][n] = sum_d W[e][d] * x[n][d]
// 128x128 tile, BK=8, 256 threads, 8x8 per thread, FFMA2 inner loop.
// ---------------------------------------------------------------------------
__global__ __launch_bounds__(256, 2)
void qkv_gemm_kernel(const float* __restrict__ x,
                     const float* __restrict__ Wq,
                     const float* __restrict__ Wk,
                     const float* __restrict__ Wv)
{
    __shared__ float As[8][128];
    __shared__ float Bs[8][128];

    const int n0  = blockIdx.x * 128;          // rows of x (b*L + l)
    const int eg0 = blockIdx.y * 128;          // global output feature tile
    const int which = eg0 >> 10;               // 0=Q,1=K,2=V
    const int e0 = eg0 & 1023;
    const float* __restrict__ W = (which == 0) ? Wq : (which == 1) ? Wk : Wv;

    const int tid = threadIdx.x;
    const int tx = tid & 15;
    const int ty = tid >> 4;

    const int lr = tid >> 1;                   // 0..127
    const int lc = (tid & 1) << 2;             // 0 or 4

    const float* Ap = W + (e0 + lr) * D_ + lc;
    const float* Bp = x + (n0 + lr) * D_ + lc;

    float4 ra = *(const float4*)Ap;
    float4 rb = *(const float4*)Bp;

    u64 acc2[8][4];                            // [i][j-pair]
#pragma unroll
    for (int i = 0; i < 8; i++)
#pragma unroll
        for (int j = 0; j < 4; j++) acc2[i][j] = 0ull;

    for (int d0 = 0; d0 < D_; d0 += 8) {
        __syncthreads();
        As[lc + 0][lr] = ra.x; As[lc + 1][lr] = ra.y;
        As[lc + 2][lr] = ra.z; As[lc + 3][lr] = ra.w;
        Bs[lc + 0][lr] = rb.x; Bs[lc + 1][lr] = rb.y;
        Bs[lc + 2][lr] = rb.z; Bs[lc + 3][lr] = rb.w;
        __syncthreads();

        if (d0 + 8 < D_) {                     // register prefetch next chunk
            ra = *(const float4*)(Ap + d0 + 8);
            rb = *(const float4*)(Bp + d0 + 8);
        }

#pragma unroll
        for (int kk = 0; kk < 8; kk++) {
            float4 a0 = *(const float4*)&As[kk][ty * 4];
            float4 a1 = *(const float4*)&As[kk][ty * 4 + 64];
            float4 b0 = *(const float4*)&Bs[kk][tx * 4];
            float4 b1 = *(const float4*)&Bs[kk][tx * 4 + 64];
            u64 bb[4] = {pk2(b0.x, b0.y), pk2(b0.z, b0.w),
                         pk2(b1.x, b1.y), pk2(b1.z, b1.w)};
            float av[8] = {a0.x, a0.y, a0.z, a0.w, a1.x, a1.y, a1.z, a1.w};
#pragma unroll
            for (int i = 0; i < 8; i++) {
                u64 ai = dup2(av[i]);
#pragma unroll
                for (int j = 0; j < 4; j++)
                    acc2[i][j] = ffma2(ai, bb[j], acc2[i][j]);
            }
        }
    }

    const int b  = n0 >> 11;                   // n tile never crosses batch
    const int l0 = n0 & (L_ - 1);

#pragma unroll
    for (int i = 0; i < 8; i++) {
        const int row = (i < 4) ? (ty * 4 + i) : (64 + ty * 4 + (i - 4));
        const int el = e0 + row;
        float2 p0 = upk2(acc2[i][0]), p1 = upk2(acc2[i][1]);
        float2 p2 = upk2(acc2[i][2]), p3 = upk2(acc2[i][3]);
        float4 v0 = make_float4(p0.x, p0.y, p1.x, p1.y);
        float4 v1 = make_float4(p2.x, p2.y, p3.x, p3.y);
        if (which == 0) {
            float* base = g_Qt + (size_t)(b * 1024 + el) * L_ + l0;
            *(float4*)(base + tx * 4)      = v0;
            *(float4*)(base + 64 + tx * 4) = v1;
        } else if (which == 1) {
            float* base = g_Kt + (size_t)(b * 1024 + el) * L_ + l0;
            *(float4*)(base + tx * 4)      = v0;
            *(float4*)(base + 64 + tx * 4) = v1;
        } else {
            const int hh = el >> 6, dh = el & 63;
            float* vb = g_V + (size_t)(b * H_ + hh) * L_ * DH_ + dh;
            float aj[8] = {p0.x, p0.y, p1.x, p1.y, p2.x, p2.y, p3.x, p3.y};
#pragma unroll
            for (int j = 0; j < 8; j++) {
                const int col = (j < 4) ? (tx * 4 + j) : (64 + tx * 4 + (j - 4));
                vb[(size_t)(l0 + col) * DH_] = aj[j];
            }
        }
    }
}

// ---------------------------------------------------------------------------
// Flash attention, fp32, causal + padding mask, tau*tanh logit cap.
// exp(30*tanh(s) - 30) = exp(-60 / (exp(2s)+1))  (exact); logits <= 30 so a
// fixed shift of 30 replaces the online max. FFMA2 in both matmul loops,
// warp-uniform fast path when the k-tile mask is all ones.
// One CTA = 64 q-rows of one (b,h). 256 threads, 4x4 micro-tile.
// ---------------------------------------------------------------------------
__global__ __launch_bounds__(256)
void attn_kernel(const int* __restrict__ mask, float* __restrict__ out)
{
    __shared__ float Qs [64 * 64];   // [d][i]
    __shared__ float KPs[64 * 64];   // K as [d][j], then P as [i][j]
    __shared__ float Vs [64 * 64];   // [j][d]

    const int qt = (int)gridDim.x - 1 - (int)blockIdx.x;  // heavy tiles first
    const int bh = blockIdx.y;
    const int b  = bh >> 4;
    const int h  = bh & 15;
    const int q0 = qt * 64;

    const int tid = threadIdx.x;
    const int tx = tid & 15;
    const int ty = tid >> 4;
    const int i0 = ty * 4;           // q rows
    const int c0 = tx * 4;           // key cols / dh cols

    const float* qsrc = g_Qt + (size_t)(bh * 64) * L_ + q0;
#pragma unroll
    for (int k = 0; k < 4; k++) {
        int idx4 = tid + k * 256;
        int d = idx4 >> 4;
        int i = (idx4 & 15) << 2;
        *(float4*)&Qs[d * 64 + i] = *(const float4*)(qsrc + (size_t)d * L_ + i);
    }

    u64 acc2[4][2];                  // O accumulators [r][dh-pair]
    float den[4] = {0.f, 0.f, 0.f, 0.f};
#pragma unroll
    for (int r = 0; r < 4; r++) { acc2[r][0] = 0ull; acc2[r][1] = 0ull; }

    const float* ksrc = g_Kt + (size_t)(bh * 64) * L_;
    const float* vsrc_base = g_V + (size_t)bh * L_ * DH_;
    const int*   mrow = mask + b * L_;

    for (int kt = 0; kt <= qt; kt++) {
        const int k0 = kt * 64;
        __syncthreads();             // prior PV done with KPs/Vs
#pragma unroll
        for (int k = 0; k < 4; k++) {
            int idx4 = tid + k * 256;
            int d = idx4 >> 4;
            int j = (idx4 & 15) << 2;
            *(float4*)&KPs[d * 64 + j] =
                *(const float4*)(ksrc + (size_t)d * L_ + k0 + j);
        }
        const float* vsrc = vsrc_base + (size_t)k0 * DH_;
#pragma unroll
        for (int k = 0; k < 4; k++) {
            int idx4 = tid + k * 256;
            *(float4*)&Vs[idx4 * 4] = *(const float4*)(vsrc + idx4 * 4);
        }
        __syncthreads();

        // S = Q K^T over d, FFMA2 with c-pairs
        u64 s2[4][2];
#pragma unroll
        for (int r = 0; r < 4; r++) { s2[r][0] = 0ull; s2[r][1] = 0ull; }
#pragma unroll 8
        for (int d = 0; d < 64; d++) {
            float4 qa = *(const float4*)&Qs[d * 64 + i0];
            float4 kb = *(const float4*)&KPs[d * 64 + c0];
            u64 kp0 = pk2(kb.x, kb.y), kp1 = pk2(kb.z, kb.w);
            float av[4] = {qa.x, qa.y, qa.z, qa.w};
#pragma unroll
            for (int r = 0; r < 4; r++) {
                u64 qd = dup2(av[r]);
                s2[r][0] = ffma2(qd, kp0, s2[r][0]);
                s2[r][1] = ffma2(qd, kp1, s2[r][1]);
            }
        }

        float s[4][4];
#pragma unroll
        for (int r = 0; r < 4; r++) {
            float2 a = upk2(s2[r][0]), bq = upk2(s2[r][1]);
            s[r][0] = a.x; s[r][1] = a.y; s[r][2] = bq.x; s[r][3] = bq.y;
        }

        int mk[4];
#pragma unroll
        for (int c = 0; c < 4; c++) mk[c] = __ldg(mrow + k0 + c0 + c);
        bool allm = (mk[0] != 0) & (mk[1] != 0) & (mk[2] != 0) & (mk[3] != 0);
        bool fast = (__ballot_sync(0xffffffffu, allm) == 0xffffffffu);

        float p[4][4];
        if (fast && kt < qt) {                 // no mask, no causal
#pragma unroll
            for (int r = 0; r < 4; r++)
#pragma unroll
                for (int c = 0; c < 4; c++) {
                    float t  = __expf(s[r][c] * 0.25f);    // exp(2*s/8)
                    float pv = __expf(__fdividef(-60.0f, t + 1.0f));
                    p[r][c] = pv;
                    den[r] += pv;
                }
        } else if (fast) {                     // diagonal tile: causal only
#pragma unroll
            for (int r = 0; r < 4; r++)
#pragma unroll
                for (int c = 0; c < 4; c++) {
                    float t  = __expf(s[r][c] * 0.25f);
                    float pv = __expf(__fdividef(-60.0f, t + 1.0f));
                    pv = ((c0 + c) <= (i0 + r)) ? pv : 0.0f;
                    p[r][c] = pv;
                    den[r] += pv;
                }
        } else {                               // general masked path
#pragma unroll
            for (int r = 0; r < 4; r++)
#pragma unroll
                for (int c = 0; c < 4; c++) {
                    float t  = __expf(s[r][c] * 0.25f);
                    float pv = __expf(__fdividef(-60.0f, t + 1.0f));
                    bool keep = (mk[c] != 0) &&
                                ((kt < qt) || ((c0 + c) <= (i0 + r)));
                    pv = keep ? pv : 0.0f;
                    p[r][c] = pv;
                    den[r] += pv;
                }
        }
        __syncthreads();             // all done reading KPs as K
#pragma unroll
        for (int r = 0; r < 4; r++)
            *(float4*)&KPs[(i0 + r) * 64 + c0] =
                make_float4(p[r][0], p[r][1], p[r][2], p[r][3]);
        __syncthreads();

        // O += P V, FFMA2 with dh-pairs
#pragma unroll 4
        for (int jj = 0; jj < 64; jj += 4) {
            float4 pa[4];
#pragma unroll
            for (int r = 0; r < 4; r++)
                pa[r] = *(const float4*)&KPs[(i0 + r) * 64 + jj];
            float4 vb[4];
#pragma unroll
            for (int u = 0; u < 4; u++)
                vb[u] = *(const float4*)&Vs[(jj + u) * 64 + c0];
            u64 vb2[4][2];
#pragma unroll
            for (int u = 0; u < 4; u++) {
                vb2[u][0] = pk2(vb[u].x, vb[u].y);
                vb2[u][1] = pk2(vb[u].z, vb[u].w);
            }
#pragma unroll
            for (int r = 0; r < 4; r++) {
                float pr[4] = {pa[r].x, pa[r].y, pa[r].z, pa[r].w};
#pragma unroll
                for (int u = 0; u < 4; u++) {
                    u64 pd = dup2(pr[u]);
                    acc2[r][0] = ffma2(pd, vb2[u][0], acc2[r][0]);
                    acc2[r][1] = ffma2(pd, vb2[u][1], acc2[r][1]);
                }
            }
        }
    }

    // row-sum reduce across the 16-lane tx group
#pragma unroll
    for (int r = 0; r < 4; r++) {
#pragma unroll
        for (int off = 8; off > 0; off >>= 1)
            den[r] += __shfl_xor_sync(0xffffffffu, den[r], off);
    }

#pragma unroll
    for (int r = 0; r < 4; r++) {
        float inv = __frcp_rn(den[r]);   // den > 0: diagonal always kept
        float2 a = upk2(acc2[r][0]), bq = upk2(acc2[r][1]);
        float4 o = make_float4(a.x * inv, a.y * inv, bq.x * inv, bq.y * inv);
        *(float4*)&out[(size_t)(b * L_ + q0 + i0 + r) * (H_ * DH_) + h * DH_ + c0] = o;
    }
}

// ---------------------------------------------------------------------------
extern "C" void kernel_launch(void* const* d_in, const int* in_sizes, int n_in,
                              void* d_out, int out_size)
{
    const float* x    = (const float*)d_in[0];
    const int*   mask = (const int*)  d_in[1];
    const float* Wq   = (const float*)d_in[2];
    const float* Wk   = (const float*)d_in[3];
    const float* Wv   = (const float*)d_in[4];
    float* out = (float*)d_out;

    qkv_gemm_kernel<<<dim3(32, 24), 256>>>(x, Wq, Wk, Wv);
    attn_kernel<<<dim3(32, 32), 256>>>(mask, out);
}

// round 8
// speedup vs baseline: 1.3388x; 1.2931x over previous
#include <cuda_runtime.h>
#include <cuda_bf16.h>

#define B_  2
#define L_  2048
#define D_  1024
#define H_  16
#define DH_ 64

typedef unsigned long long u64;
typedef unsigned int u32;

// ===================== PTX helpers (base sm_103 ISA only) =====================
__device__ __forceinline__ u32 smem_u32(const void* p) {
    u32 a;
    asm("{ .reg .u64 t; cvta.to.shared.u64 t, %1; cvt.u32.u64 %0, t; }"
        : "=r"(a) : "l"(p));
    return a;
}
__device__ __forceinline__ void ldsm4(u32* r, u32 addr) {
    asm volatile("ldmatrix.sync.aligned.m8n8.x4.shared.b16 {%0,%1,%2,%3},[%4];"
                 : "=r"(r[0]), "=r"(r[1]), "=r"(r[2]), "=r"(r[3]) : "r"(addr));
}
__device__ __forceinline__ void mma16816(float* c, const u32* a, const u32* b) {
    asm volatile(
        "mma.sync.aligned.m16n8k16.row.col.f32.bf16.bf16.f32 "
        "{%0,%1,%2,%3},{%4,%5,%6,%7},{%8,%9},{%0,%1,%2,%3};"
        : "+f"(c[0]), "+f"(c[1]), "+f"(c[2]), "+f"(c[3])
        : "r"(a[0]), "r"(a[1]), "r"(a[2]), "r"(a[3]), "r"(b[0]), "r"(b[1]));
}
__device__ __forceinline__ void cp16(u32 saddr, const void* gaddr) {
    asm volatile("cp.async.cg.shared.global [%0],[%1],16;"
                 :: "r"(saddr), "l"(gaddr));
}
#define CP_COMMIT() asm volatile("cp.async.commit_group;" ::: "memory")
#define CP_WAIT1()  asm volatile("cp.async.wait_group 1;" ::: "memory")
#define CP_WAIT0()  asm volatile("cp.async.wait_group 0;" ::: "memory")

// ---- packed f32x2 helpers (attention kernel) ----
__device__ __forceinline__ u64 pk2(float lo, float hi) {
    u64 r; asm("mov.b64 %0,{%1,%2};" : "=l"(r) : "f"(lo), "f"(hi)); return r;
}
__device__ __forceinline__ u64 dup2(float v) { return pk2(v, v); }
__device__ __forceinline__ u64 ffma2(u64 a, u64 b, u64 c) {
    u64 d; asm("fma.rn.f32x2 %0,%1,%2,%3;" : "=l"(d) : "l"(a), "l"(b), "l"(c));
    return d;
}
__device__ __forceinline__ float2 upk2(u64 v) {
    float lo, hi; asm("mov.b64 {%0,%1},%2;" : "=f"(lo), "=f"(hi) : "l"(v));
    return make_float2(lo, hi);
}

// ===================== device scratch =====================
__device__ float g_Qt[B_ * H_ * DH_ * L_];
__device__ float g_Kt[B_ * H_ * DH_ * L_];
__device__ float g_V [B_ * H_ * L_ * DH_];
// bf16 hi/lo splits: W concat [3072][1024], x [4096][1024]
__device__ unsigned short g_Wh[3072 * 1024];
__device__ unsigned short g_Wl[3072 * 1024];
__device__ unsigned short g_xh[4096 * 1024];
__device__ unsigned short g_xl[4096 * 1024];

// ===================== split-prep: fp32 -> bf16 hi + bf16 lo =====================
__global__ void split_kernel(const float* __restrict__ src,
                             unsigned short* __restrict__ dh,
                             unsigned short* __restrict__ dl, int n4)
{
    int i = blockIdx.x * blockDim.x + threadIdx.x;
    if (i >= n4) return;
    float4 v = ((const float4*)src)[i];
    float f[4] = {v.x, v.y, v.z, v.w};
    u32 hw[4], lw[4];
#pragma unroll
    for (int k = 0; k < 4; k++) {
        __nv_bfloat16 h = __float2bfloat16(f[k]);
        __nv_bfloat16 l = __float2bfloat16(f[k] - __bfloat162float(h));
        hw[k] = __bfloat16_as_ushort(h);
        lw[k] = __bfloat16_as_ushort(l);
    }
    ((uint2*)dh)[i] = make_uint2(hw[0] | (hw[1] << 16), hw[2] | (hw[3] << 16));
    ((uint2*)dl)[i] = make_uint2(lw[0] | (lw[1] << 16), lw[2] | (lw[3] << 16));
}

// ===================== HMMA bf16x3 projection GEMM =====================
// C[e][n] = sum_d W[e][d]*x[n][d].  CTA tile 128(e) x 128(n), K-chunk 64.
// 8 warps: wm = wid&1 (64 e-rows), wn = wid>>1 (32 n-cols). bf16x3 split.
#define TSTRIDE 72                    // b16 per smem row (64 data + 8 pad)
#define TILE_B  (128 * TSTRIDE * 2)   // 18432 bytes per tile
#define STAGE_B (4 * TILE_B)          // Ah,Al,Bh,Bl = 73728
#define MM_SMEM (2 * STAGE_B)         // double buffered = 147456

__global__ __launch_bounds__(256, 1) void mm_kernel()
{
    extern __shared__ char dsm[];
    const int tid = threadIdx.x, wid = tid >> 5, lane = tid & 31;
    const int n0  = blockIdx.x * 128;
    const int eg0 = blockIdx.y * 128;
    const int which = eg0 >> 10;      // 0=Q,1=K,2=V
    const int e0 = eg0 & 1023;
    const int b  = n0 >> 11;
    const int l0 = n0 & (L_ - 1);
    const int wm = wid & 1, wn = wid >> 1;

    const u32 smem0 = smem_u32(dsm);
    const unsigned short* gsrc[4] = {
        g_Wh + (size_t)eg0 * 1024, g_Wl + (size_t)eg0 * 1024,
        g_xh + (size_t)n0  * 1024, g_xl + (size_t)n0  * 1024 };

    // ---- async load of one K-chunk into stage s ----
    auto issue = [&](int c, int s) {
        const int kc = c * 64;
        const u32 sb = smem0 + s * STAGE_B;
#pragma unroll
        for (int t = 0; t < 4; t++) {
#pragma unroll
            for (int it = 0; it < 4; it++) {
                int g = tid + it * 256;          // 0..1023 16B segments
                int row = g >> 3, seg = g & 7;
                cp16(sb + t * TILE_B + row * (TSTRIDE * 2) + seg * 16,
                     gsrc[t] + (size_t)row * 1024 + kc + seg * 8);
            }
        }
        CP_COMMIT();
    };

    float acc[4][4][4];
#pragma unroll
    for (int i = 0; i < 4; i++)
#pragma unroll
        for (int j = 0; j < 4; j++)
#pragma unroll
            for (int k = 0; k < 4; k++) acc[i][j][k] = 0.0f;

    issue(0, 0);
    for (int c = 0; c < 16; c++) {
        if (c + 1 < 16) issue(c + 1, (c + 1) & 1);
        if (c + 1 < 16) CP_WAIT1(); else CP_WAIT0();
        __syncthreads();

        const u32 sA  = smem0 + (c & 1) * STAGE_B;
        const u32 sAl = sA + TILE_B;
        const u32 sB  = sA + 2 * TILE_B;
        const u32 sBl = sA + 3 * TILE_B;

        const int arow = 64 * wm + (lane & 7) + ((lane >> 3) & 1) * 8;
        const int brow = 32 * wn + (lane & 7) + ((lane >> 3) & 1) * 8;
        const u32 koffB = ((lane >> 4) & 1) * 16;

#pragma unroll
        for (int ks = 0; ks < 4; ks++) {
            const u32 ko = ks * 32 + koffB;
            u32 Ah[4][4], Al[4][4], Bh[4][2], Bl[4][2];
#pragma unroll
            for (int am = 0; am < 4; am++) {
                u32 ad = (arow + am * 16) * (TSTRIDE * 2) + ko;
                ldsm4(Ah[am], sA  + ad);
                ldsm4(Al[am], sAl + ad);
            }
#pragma unroll
            for (int an2 = 0; an2 < 2; an2++) {
                u32 r[4], ad = (brow + an2 * 16) * (TSTRIDE * 2) + ko;
                ldsm4(r, sB + ad);
                Bh[an2 * 2][0] = r[0]; Bh[an2 * 2 + 1][0] = r[1];
                Bh[an2 * 2][1] = r[2]; Bh[an2 * 2 + 1][1] = r[3];
                ldsm4(r, sBl + ad);
                Bl[an2 * 2][0] = r[0]; Bl[an2 * 2 + 1][0] = r[1];
                Bl[an2 * 2][1] = r[2]; Bl[an2 * 2 + 1][1] = r[3];
            }
#pragma unroll
            for (int am = 0; am < 4; am++)
#pragma unroll
                for (int an = 0; an < 4; an++) {
                    mma16816(acc[am][an], Ah[am], Bh[an]);
                    mma16816(acc[am][an], Ah[am], Bl[an]);
                    mma16816(acc[am][an], Al[am], Bh[an]);
                }
        }
        __syncthreads();   // all warps done with this stage before reload
    }

    // ---- epilogue through fp32 smem stage [128][132] ----
    float* stage = (float*)dsm;
    const int g = lane >> 2, tg = lane & 3;
#pragma unroll
    for (int am = 0; am < 4; am++)
#pragma unroll
        for (int an = 0; an < 4; an++) {
            int row = 64 * wm + am * 16 + g;
            int col = 32 * wn + an * 8 + tg * 2;
            *(float2*)&stage[row * 132 + col] =
                make_float2(acc[am][an][0], acc[am][an][1]);
            *(float2*)&stage[(row + 8) * 132 + col] =
                make_float2(acc[am][an][2], acc[am][an][3]);
        }
    __syncthreads();

    if (which == 2) {
#pragma unroll
        for (int it = 0; it < 16; it++) {
            int r = wid + it * 8;
            int el = e0 + r;
            int hh = el >> 6, dh = el & 63;
            float4 v = *(float4*)&stage[r * 132 + lane * 4];
            float* vb = g_V + (size_t)(b * H_ + hh) * L_ * DH_ + dh;
            vb[(size_t)(l0 + lane * 4 + 0) * DH_] = v.x;
            vb[(size_t)(l0 + lane * 4 + 1) * DH_] = v.y;
            vb[(size_t)(l0 + lane * 4 + 2) * DH_] = v.z;
            vb[(size_t)(l0 + lane * 4 + 3) * DH_] = v.w;
        }
    } else {
        float* G = (which == 0) ? g_Qt : g_Kt;
        float* grow = G + (size_t)(b * 1024 + e0) * L_ + l0;
#pragma unroll
        for (int it = 0; it < 16; it++) {
            int r = wid + it * 8;
            float4 v = *(float4*)&stage[r * 132 + lane * 4];
            *(float4*)(grow + (size_t)r * L_ + lane * 4) = v;
        }
    }
}

// ===================== flash attention (unchanged from R6) =====================
__global__ __launch_bounds__(256)
void attn_kernel(const int* __restrict__ mask, float* __restrict__ out)
{
    __shared__ float Qs [64 * 64];
    __shared__ float KPs[64 * 64];
    __shared__ float Vs [64 * 64];

    const int qt = (int)gridDim.x - 1 - (int)blockIdx.x;
    const int bh = blockIdx.y;
    const int b  = bh >> 4;
    const int h  = bh & 15;
    const int q0 = qt * 64;

    const int tid = threadIdx.x;
    const int tx = tid & 15;
    const int ty = tid >> 4;
    const int i0 = ty * 4;
    const int c0 = tx * 4;

    const float* qsrc = g_Qt + (size_t)(bh * 64) * L_ + q0;
#pragma unroll
    for (int k = 0; k < 4; k++) {
        int idx4 = tid + k * 256;
        int d = idx4 >> 4;
        int i = (idx4 & 15) << 2;
        *(float4*)&Qs[d * 64 + i] = *(const float4*)(qsrc + (size_t)d * L_ + i);
    }

    u64 acc2[4][2];
    float den[4] = {0.f, 0.f, 0.f, 0.f};
#pragma unroll
    for (int r = 0; r < 4; r++) { acc2[r][0] = 0ull; acc2[r][1] = 0ull; }

    const float* ksrc = g_Kt + (size_t)(bh * 64) * L_;
    const float* vsrc_base = g_V + (size_t)bh * L_ * DH_;
    const int*   mrow = mask + b * L_;

    for (int kt = 0; kt <= qt; kt++) {
        const int k0 = kt * 64;
        __syncthreads();
#pragma unroll
        for (int k = 0; k < 4; k++) {
            int idx4 = tid + k * 256;
            int d = idx4 >> 4;
            int j = (idx4 & 15) << 2;
            *(float4*)&KPs[d * 64 + j] =
                *(const float4*)(ksrc + (size_t)d * L_ + k0 + j);
        }
        const float* vsrc = vsrc_base + (size_t)k0 * DH_;
#pragma unroll
        for (int k = 0; k < 4; k++) {
            int idx4 = tid + k * 256;
            *(float4*)&Vs[idx4 * 4] = *(const float4*)(vsrc + idx4 * 4);
        }
        __syncthreads();

        u64 s2[4][2];
#pragma unroll
        for (int r = 0; r < 4; r++) { s2[r][0] = 0ull; s2[r][1] = 0ull; }
#pragma unroll 8
        for (int d = 0; d < 64; d++) {
            float4 qa = *(const float4*)&Qs[d * 64 + i0];
            float4 kb = *(const float4*)&KPs[d * 64 + c0];
            u64 kp0 = pk2(kb.x, kb.y), kp1 = pk2(kb.z, kb.w);
            float av[4] = {qa.x, qa.y, qa.z, qa.w};
#pragma unroll
            for (int r = 0; r < 4; r++) {
                u64 qd = dup2(av[r]);
                s2[r][0] = ffma2(qd, kp0, s2[r][0]);
                s2[r][1] = ffma2(qd, kp1, s2[r][1]);
            }
        }

        float s[4][4];
#pragma unroll
        for (int r = 0; r < 4; r++) {
            float2 a = upk2(s2[r][0]), bq = upk2(s2[r][1]);
            s[r][0] = a.x; s[r][1] = a.y; s[r][2] = bq.x; s[r][3] = bq.y;
        }

        int mk[4];
#pragma unroll
        for (int c = 0; c < 4; c++) mk[c] = __ldg(mrow + k0 + c0 + c);
        bool allm = (mk[0] != 0) & (mk[1] != 0) & (mk[2] != 0) & (mk[3] != 0);
        bool fast = (__ballot_sync(0xffffffffu, allm) == 0xffffffffu);

        float p[4][4];
        if (fast && kt < qt) {
#pragma unroll
            for (int r = 0; r < 4; r++)
#pragma unroll
                for (int c = 0; c < 4; c++) {
                    float t  = __expf(s[r][c] * 0.25f);
                    float pv = __expf(__fdividef(-60.0f, t + 1.0f));
                    p[r][c] = pv; den[r] += pv;
                }
        } else if (fast) {
#pragma unroll
            for (int r = 0; r < 4; r++)
#pragma unroll
                for (int c = 0; c < 4; c++) {
                    float t  = __expf(s[r][c] * 0.25f);
                    float pv = __expf(__fdividef(-60.0f, t + 1.0f));
                    pv = ((c0 + c) <= (i0 + r)) ? pv : 0.0f;
                    p[r][c] = pv; den[r] += pv;
                }
        } else {
#pragma unroll
            for (int r = 0; r < 4; r++)
#pragma unroll
                for (int c = 0; c < 4; c++) {
                    float t  = __expf(s[r][c] * 0.25f);
                    float pv = __expf(__fdividef(-60.0f, t + 1.0f));
                    bool keep = (mk[c] != 0) &&
                                ((kt < qt) || ((c0 + c) <= (i0 + r)));
                    pv = keep ? pv : 0.0f;
                    p[r][c] = pv; den[r] += pv;
                }
        }
        __syncthreads();
#pragma unroll
        for (int r = 0; r < 4; r++)
            *(float4*)&KPs[(i0 + r) * 64 + c0] =
                make_float4(p[r][0], p[r][1], p[r][2], p[r][3]);
        __syncthreads();

#pragma unroll 4
        for (int jj = 0; jj < 64; jj += 4) {
            float4 pa[4];
#pragma unroll
            for (int r = 0; r < 4; r++)
                pa[r] = *(const float4*)&KPs[(i0 + r) * 64 + jj];
            float4 vb[4];
#pragma unroll
            for (int u = 0; u < 4; u++)
                vb[u] = *(const float4*)&Vs[(jj + u) * 64 + c0];
            u64 vb2[4][2];
#pragma unroll
            for (int u = 0; u < 4; u++) {
                vb2[u][0] = pk2(vb[u].x, vb[u].y);
                vb2[u][1] = pk2(vb[u].z, vb[u].w);
            }
#pragma unroll
            for (int r = 0; r < 4; r++) {
                float pr[4] = {pa[r].x, pa[r].y, pa[r].z, pa[r].w};
#pragma unroll
                for (int u = 0; u < 4; u++) {
                    u64 pd = dup2(pr[u]);
                    acc2[r][0] = ffma2(pd, vb2[u][0], acc2[r][0]);
                    acc2[r][1] = ffma2(pd, vb2[u][1], acc2[r][1]);
                }
            }
        }
    }

#pragma unroll
    for (int r = 0; r < 4; r++) {
#pragma unroll
        for (int off = 8; off > 0; off >>= 1)
            den[r] += __shfl_xor_sync(0xffffffffu, den[r], off);
    }

#pragma unroll
    for (int r = 0; r < 4; r++) {
        float inv = __frcp_rn(den[r]);
        float2 a = upk2(acc2[r][0]), bq = upk2(acc2[r][1]);
        float4 o = make_float4(a.x * inv, a.y * inv, bq.x * inv, bq.y * inv);
        *(float4*)&out[(size_t)(b * L_ + q0 + i0 + r) * (H_ * DH_) + h * DH_ + c0] = o;
    }
}

// ---------------------------------------------------------------------------
extern "C" void kernel_launch(void* const* d_in, const int* in_sizes, int n_in,
                              void* d_out, int out_size)
{
    const float* x    = (const float*)d_in[0];
    const int*   mask = (const int*)  d_in[1];
    const float* Wq   = (const float*)d_in[2];
    const float* Wk   = (const float*)d_in[3];
    const float* Wv   = (const float*)d_in[4];
    float* out = (float*)d_out;

    unsigned short *wh, *wl, *xh, *xl;
    cudaGetSymbolAddress((void**)&wh, g_Wh);
    cudaGetSymbolAddress((void**)&wl, g_Wl);
    cudaGetSymbolAddress((void**)&xh, g_xh);
    cudaGetSymbolAddress((void**)&xl, g_xl);

    static int smem_set = 0;
    if (!smem_set) {
        cudaFuncSetAttribute(mm_kernel,
                             cudaFuncAttributeMaxDynamicSharedMemorySize, MM_SMEM);
        smem_set = 1;
    }

    split_kernel<<<4096, 256>>>(x,  xh, xl, 4096 * 1024 / 4);
    split_kernel<<<1024, 256>>>(Wq, wh, wl, 1024 * 1024 / 4);
    split_kernel<<<1024, 256>>>(Wk, wh + 1024 * 1024, wl + 1024 * 1024, 1024 * 1024 / 4);
    split_kernel<<<1024, 256>>>(Wv, wh + 2048 * 1024, wl + 2048 * 1024, 1024 * 1024 / 4);
    mm_kernel<<<dim3(32, 24), 256, MM_SMEM>>>();
    attn_kernel<<<dim3(32, 32), 256>>>(mask, out);
}

// round 13
// speedup vs baseline: 2.0175x; 1.5070x over previous
#include <cuda_runtime.h>
#include <cuda_bf16.h>

#define B_  2
#define L_  2048
#define D_  1024
#define H_  16
#define DH_ 64

typedef unsigned long long u64;
typedef unsigned int u32;

// ===================== PTX helpers (base sm_103 ISA only) =====================
__device__ __forceinline__ u32 smem_u32(const void* p) {
    u32 a;
    asm("{ .reg .u64 t; cvta.to.shared.u64 t, %1; cvt.u32.u64 %0, t; }"
        : "=r"(a) : "l"(p));
    return a;
}
__device__ __forceinline__ void ldsm4(u32* r, u32 addr) {
    asm volatile("ldmatrix.sync.aligned.m8n8.x4.shared.b16 {%0,%1,%2,%3},[%4];"
                 : "=r"(r[0]), "=r"(r[1]), "=r"(r[2]), "=r"(r[3]) : "r"(addr));
}
__device__ __forceinline__ void mma16816(float* c, const u32* a, const u32* b) {
    asm volatile(
        "mma.sync.aligned.m16n8k16.row.col.f32.bf16.bf16.f32 "
        "{%0,%1,%2,%3},{%4,%5,%6,%7},{%8,%9},{%0,%1,%2,%3};"
        : "+f"(c[0]), "+f"(c[1]), "+f"(c[2]), "+f"(c[3])
        : "r"(a[0]), "r"(a[1]), "r"(a[2]), "r"(a[3]), "r"(b[0]), "r"(b[1]));
}
__device__ __forceinline__ void cp16(u32 saddr, const void* gaddr) {
    asm volatile("cp.async.cg.shared.global [%0],[%1],16;"
                 :: "r"(saddr), "l"(gaddr));
}
#define CP_COMMIT() asm volatile("cp.async.commit_group;" ::: "memory")
#define CP_WAIT1()  asm volatile("cp.async.wait_group 1;" ::: "memory")
#define CP_WAIT0()  asm volatile("cp.async.wait_group 0;" ::: "memory")

// pack two fp32 -> bf16x2 (upper = a, lower = b)
__device__ __forceinline__ u32 cvt2(float a, float b) {
    u32 r; asm("cvt.rn.bf16x2.f32 %0,%1,%2;" : "=r"(r) : "f"(a), "f"(b));
    return r;
}
__device__ __forceinline__ float lo_f(u32 w) { return __uint_as_float(w << 16); }
__device__ __forceinline__ float hi_f(u32 w) { return __uint_as_float(w & 0xffff0000u); }

// ===================== device scratch =====================
// W/x bf16 splits for the projection GEMM
__device__ unsigned short g_Wh[3072 * 1024];
__device__ unsigned short g_Wl[3072 * 1024];
__device__ unsigned short g_xh[4096 * 1024];
__device__ unsigned short g_xl[4096 * 1024];
// attention operands, bf16 hi/lo:
// Q,K: [bh][l][64]  (d contiguous)   V: [bh][dh][2048] (key contiguous)
__device__ unsigned short g_Qh[32 * 2048 * 64], g_Ql[32 * 2048 * 64];
__device__ unsigned short g_Kh[32 * 2048 * 64], g_Kl[32 * 2048 * 64];
__device__ unsigned short g_Vh[32 * 64 * 2048], g_Vl[32 * 64 * 2048];

// ===================== split-prep: fp32 -> bf16 hi + bf16 lo =====================
__global__ void split_kernel(const float* __restrict__ src,
                             unsigned short* __restrict__ dh,
                             unsigned short* __restrict__ dl, int n4)
{
    int i = blockIdx.x * blockDim.x + threadIdx.x;
    if (i >= n4) return;
    float4 v = ((const float4*)src)[i];
    float f[4] = {v.x, v.y, v.z, v.w};
    u32 hw[4], lw[4];
#pragma unroll
    for (int k = 0; k < 4; k++) {
        __nv_bfloat16 h = __float2bfloat16(f[k]);
        __nv_bfloat16 l = __float2bfloat16(f[k] - __bfloat162float(h));
        hw[k] = __bfloat16_as_ushort(h);
        lw[k] = __bfloat16_as_ushort(l);
    }
    ((uint2*)dh)[i] = make_uint2(hw[0] | (hw[1] << 16), hw[2] | (hw[3] << 16));
    ((uint2*)dl)[i] = make_uint2(lw[0] | (lw[1] << 16), lw[2] | (lw[3] << 16));
}

// ===================== HMMA bf16x3 projection GEMM =====================
#define TSTRIDE 72
#define TILE_B  (128 * TSTRIDE * 2)
#define STAGE_B (4 * TILE_B)
#define MM_SMEM (2 * STAGE_B)

__global__ __launch_bounds__(256, 1) void mm_kernel()
{
    extern __shared__ char dsm[];
    const int tid = threadIdx.x, wid = tid >> 5, lane = tid & 31;
    const int n0  = blockIdx.x * 128;
    const int eg0 = blockIdx.y * 128;
    const int which = eg0 >> 10;      // 0=Q,1=K,2=V
    const int e0 = eg0 & 1023;
    const int b  = n0 >> 11;
    const int l0 = n0 & (L_ - 1);
    const int wm = wid & 1, wn = wid >> 1;

    const u32 smem0 = smem_u32(dsm);
    const unsigned short* gsrc[4] = {
        g_Wh + (size_t)eg0 * 1024, g_Wl + (size_t)eg0 * 1024,
        g_xh + (size_t)n0  * 1024, g_xl + (size_t)n0  * 1024 };

    auto issue = [&](int c, int s) {
        const int kc = c * 64;
        const u32 sb = smem0 + s * STAGE_B;
#pragma unroll
        for (int t = 0; t < 4; t++) {
#pragma unroll
            for (int it = 0; it < 4; it++) {
                int g = tid + it * 256;
                int row = g >> 3, seg = g & 7;
                cp16(sb + t * TILE_B + row * (TSTRIDE * 2) + seg * 16,
                     gsrc[t] + (size_t)row * 1024 + kc + seg * 8);
            }
        }
        CP_COMMIT();
    };

    float acc[4][4][4];
#pragma unroll
    for (int i = 0; i < 4; i++)
#pragma unroll
        for (int j = 0; j < 4; j++)
#pragma unroll
            for (int k = 0; k < 4; k++) acc[i][j][k] = 0.0f;

    issue(0, 0);
    for (int c = 0; c < 16; c++) {
        if (c + 1 < 16) issue(c + 1, (c + 1) & 1);
        if (c + 1 < 16) CP_WAIT1(); else CP_WAIT0();
        __syncthreads();

        const u32 sA  = smem0 + (c & 1) * STAGE_B;
        const u32 sAl = sA + TILE_B;
        const u32 sB  = sA + 2 * TILE_B;
        const u32 sBl = sA + 3 * TILE_B;

        const int arow = 64 * wm + (lane & 15);
        const int brow = 32 * wn + (lane & 15);
        const u32 koffB = ((lane >> 4) & 1) * 16;

#pragma unroll
        for (int ks = 0; ks < 4; ks++) {
            const u32 ko = ks * 32 + koffB;
            u32 Ah[4][4], Al[4][4], Bh[4][2], Bl[4][2];
#pragma unroll
            for (int am = 0; am < 4; am++) {
                u32 ad = (arow + am * 16) * (TSTRIDE * 2) + ko;
                ldsm4(Ah[am], sA  + ad);
                ldsm4(Al[am], sAl + ad);
            }
#pragma unroll
            for (int an2 = 0; an2 < 2; an2++) {
                u32 r[4], ad = (brow + an2 * 16) * (TSTRIDE * 2) + ko;
                ldsm4(r, sB + ad);
                Bh[an2 * 2][0] = r[0]; Bh[an2 * 2 + 1][0] = r[1];
                Bh[an2 * 2][1] = r[2]; Bh[an2 * 2 + 1][1] = r[3];
                ldsm4(r, sBl + ad);
                Bl[an2 * 2][0] = r[0]; Bl[an2 * 2 + 1][0] = r[1];
                Bl[an2 * 2][1] = r[2]; Bl[an2 * 2 + 1][1] = r[3];
            }
#pragma unroll
            for (int am = 0; am < 4; am++)
#pragma unroll
                for (int an = 0; an < 4; an++) {
                    mma16816(acc[am][an], Ah[am], Bh[an]);
                    mma16816(acc[am][an], Ah[am], Bl[an]);
                    mma16816(acc[am][an], Al[am], Bh[an]);
                }
        }
        __syncthreads();
    }

    const int g = lane >> 2, tg = lane & 3;

    if (which == 2) {
        // V: acc orientation (row=feature->dh, col=l->key) matches [dh][key]
#pragma unroll
        for (int am = 0; am < 4; am++)
#pragma unroll
            for (int an = 0; an < 4; an++) {
                int el = e0 + 64 * wm + am * 16 + g;    // +8 stays in same head
                int h = el >> 6, dh = el & 63;
                int col = l0 + 32 * wn + an * 8 + tg * 2;
                size_t base0 = ((size_t)(b * 16 + h) * 64 + dh) * 2048 + col;
                size_t base1 = base0 + (size_t)8 * 2048;
                u32 w0 = cvt2(acc[am][an][1], acc[am][an][0]);
                u32 w1 = cvt2(acc[am][an][3], acc[am][an][2]);
                *(u32*)&g_Vh[base0] = w0;
                *(u32*)&g_Vh[base1] = w1;
                u32 l0w = cvt2(acc[am][an][1] - hi_f(w0), acc[am][an][0] - lo_f(w0));
                u32 l1w = cvt2(acc[am][an][3] - hi_f(w1), acc[am][an][2] - lo_f(w1));
                *(u32*)&g_Vl[base0] = l0w;
                *(u32*)&g_Vl[base1] = l1w;
            }
    } else {
        // Q/K: transpose to [l][e] through fp32 smem, then convert to bf16 hi/lo
        float* stage = (float*)dsm;
#pragma unroll
        for (int am = 0; am < 4; am++)
#pragma unroll
            for (int an = 0; an < 4; an++) {
                int e = 64 * wm + am * 16 + g;
                int l = 32 * wn + an * 8 + tg * 2;
                stage[l * 132 + e]           = acc[am][an][0];
                stage[(l + 1) * 132 + e]     = acc[am][an][1];
                stage[l * 132 + e + 8]       = acc[am][an][2];
                stage[(l + 1) * 132 + e + 8] = acc[am][an][3];
            }
        __syncthreads();
        const int l = tid >> 1, half = tid & 1;
        const int h = (e0 >> 6) + half;
        unsigned short* dsth = ((which == 0) ? g_Qh : g_Kh)
                             + ((size_t)(b * 16 + h) * 2048 + l0 + l) * 64;
        unsigned short* dstl = ((which == 0) ? g_Ql : g_Kl)
                             + ((size_t)(b * 16 + h) * 2048 + l0 + l) * 64;
#pragma unroll
        for (int i = 0; i < 16; i++) {
            float4 v = *(float4*)&stage[l * 132 + half * 64 + i * 4];
            u32 w0 = cvt2(v.y, v.x), w1 = cvt2(v.w, v.z);
            *(uint2*)&dsth[i * 4] = make_uint2(w0, w1);
            u32 r0 = cvt2(v.y - hi_f(w0), v.x - lo_f(w0));
            u32 r1 = cvt2(v.w - hi_f(w1), v.z - lo_f(w1));
            *(uint2*)&dstl[i * 4] = make_uint2(r0, r1);
        }
    }
}

// ===================== HMMA flash attention =====================
// CTA = one bh x 128 q-rows; 8 warps x 16 q-rows; key tiles of 64.
// Fixed-shift softmax: p = exp(-60/(e^{2s}+1)), logits <= tau=30 so no online max.
// bf16x3 split on both QK^T and PV; P stays in registers (C-frag == A-frag trick).
#define AQ_B   18432              // 128 rows * 144B, per hi/lo
#define AKV_B  9216               // 64 rows * 144B
#define ASTG_B (4 * AKV_B)        // Kh,Kl,Vh,Vl
#define ATT_SMEM (2 * AQ_B + 2 * ASTG_B)   // 110592

__global__ __launch_bounds__(256, 1)
void attn_kernel(const int* __restrict__ mask, float* __restrict__ out)
{
    extern __shared__ char dsm[];
    const int tid = threadIdx.x, w = tid >> 5, lane = tid & 31;
    const int qt = 15 - (int)blockIdx.x;       // heavy tiles first
    const int bh = blockIdx.y;
    const int b  = bh >> 4;
    const int h  = bh & 15;
    const int q0 = qt * 128;
    const int bL = b * L_;

    const u32 smem0 = smem_u32(dsm);
    const u32 sQh = smem0, sQl = smem0 + AQ_B;

    const int g  = lane >> 2, tg = lane & 3;
    const int frow = lane & 15;                 // ldmatrix row within 16
    const u32 koff = ((lane >> 4) & 1) * 16;
    const int qbase = q0 + w * 16;
    const int qlo = qbase, qhi = qbase + 15;

    // --- initial loads: Q tile (hi+lo) + first K/V stage, one cp.async group ---
    {
        const unsigned short* gq  = g_Qh + ((size_t)bh * 2048 + q0) * 64;
        const unsigned short* gql = g_Ql + ((size_t)bh * 2048 + q0) * 64;
#pragma unroll
        for (int it = 0; it < 4; it++) {
            int idx = tid + it * 256;           // 1024 segs
            int row = idx >> 3, seg = idx & 7;
            cp16(sQh + row * 144 + seg * 16, gq  + (size_t)row * 64 + seg * 8);
            cp16(sQl + row * 144 + seg * 16, gql + (size_t)row * 64 + seg * 8);
        }
    }
    auto issue = [&](int kt, int s) {
        const int k0 = kt * 64;
        const u32 sb = smem0 + 2 * AQ_B + s * ASTG_B;
#pragma unroll
        for (int it = 0; it < 2; it++) {
            int idx = tid + it * 256;           // 512 segs per sub-tile
            int row = idx >> 3, seg = idx & 7;
            cp16(sb + row * 144 + seg * 16,
                 g_Kh + ((size_t)bh * 2048 + k0 + row) * 64 + seg * 8);
            cp16(sb + AKV_B + row * 144 + seg * 16,
                 g_Kl + ((size_t)bh * 2048 + k0 + row) * 64 + seg * 8);
            cp16(sb + 2 * AKV_B + row * 144 + seg * 16,
                 g_Vh + ((size_t)bh * 64 + row) * 2048 + k0 + seg * 8);
            cp16(sb + 3 * AKV_B + row * 144 + seg * 16,
                 g_Vl + ((size_t)bh * 64 + row) * 2048 + k0 + seg * 8);
        }
    };
    issue(0, 0);
    CP_COMMIT();

    u32 Qh[4][4], Ql[4][4];
    float oacc[8][4];
    float den0 = 0.f, den1 = 0.f;
#pragma unroll
    for (int n = 0; n < 8; n++)
#pragma unroll
        for (int k = 0; k < 4; k++) oacc[n][k] = 0.0f;

    const int nt = 2 * qt + 2;
    for (int kt = 0; kt < nt; kt++) {
        if (kt + 1 < nt) { issue(kt + 1, (kt + 1) & 1); CP_COMMIT(); CP_WAIT1(); }
        else CP_WAIT0();
        __syncthreads();

        if (kt == 0) {                          // hoist Q fragments once
#pragma unroll
            for (int ks = 0; ks < 4; ks++) {
                // FIX(R11): Q is per-warp — include this warp's 16-row offset.
                u32 ad = (u32)(w * 16 + frow) * 144 + ks * 32 + koff;
                ldsm4(Qh[ks], sQh + ad);
                ldsm4(Ql[ks], sQl + ad);
            }
        }

        const int k0 = kt * 64;
        if (k0 <= qhi) {                        // warp-uniform liveness
            const u32 sb = smem0 + 2 * AQ_B + (kt & 1) * ASTG_B;
            const u32 sKh = sb, sKl = sb + AKV_B, sVh = sb + 2 * AKV_B, sVl = sb + 3 * AKV_B;

            // ---- S = Q K^T (bf16x3) ----
            float sacc[8][4];
#pragma unroll
            for (int n = 0; n < 8; n++)
#pragma unroll
                for (int k = 0; k < 4; k++) sacc[n][k] = 0.0f;
#pragma unroll
            for (int ks = 0; ks < 4; ks++) {
#pragma unroll
                for (int an2 = 0; an2 < 4; an2++) {
                    u32 rh[4], rl[4];
                    u32 ad = (frow + an2 * 16) * 144 + ks * 32 + koff;
                    ldsm4(rh, sKh + ad);
                    ldsm4(rl, sKl + ad);
                    u32 b0h[2] = {rh[0], rh[2]}, b1h[2] = {rh[1], rh[3]};
                    u32 b0l[2] = {rl[0], rl[2]}, b1l[2] = {rl[1], rl[3]};
                    mma16816(sacc[an2 * 2],     Qh[ks], b0h);
                    mma16816(sacc[an2 * 2],     Qh[ks], b0l);
                    mma16816(sacc[an2 * 2],     Ql[ks], b0h);
                    mma16816(sacc[an2 * 2 + 1], Qh[ks], b1h);
                    mma16816(sacc[an2 * 2 + 1], Qh[ks], b1l);
                    mma16816(sacc[an2 * 2 + 1], Ql[ks], b1h);
                }
            }

            // ---- softmax (fixed shift tau) ----
            const bool noc = (k0 + 63 <= qlo);  // tile fully below diagonal
            int mw = __ldg(mask + bL + k0 + lane * 2) &
                     __ldg(mask + bL + k0 + lane * 2 + 1);
            const bool fastm = (__ballot_sync(0xffffffffu, mw != 0) == 0xffffffffu);

#pragma unroll
            for (int n = 0; n < 8; n++) {
                float p[4];
#pragma unroll
                for (int k = 0; k < 4; k++) {
                    float t = __expf(sacc[n][k] * 0.25f);          // e^{2 s/8}
                    p[k] = __expf(__fdividef(-60.0f, t + 1.0f));
                }
                const int key = k0 + n * 8 + tg * 2;
                if (!noc) {
                    if (key     > qbase + g)     p[0] = 0.f;
                    if (key + 1 > qbase + g)     p[1] = 0.f;
                    if (key     > qbase + g + 8) p[2] = 0.f;
                    if (key + 1 > qbase + g + 8) p[3] = 0.f;
                }
                if (!fastm) {
                    bool m0 = __ldg(mask + bL + key) != 0;
                    bool m1 = __ldg(mask + bL + key + 1) != 0;
                    if (!m0) { p[0] = 0.f; p[2] = 0.f; }
                    if (!m1) { p[1] = 0.f; p[3] = 0.f; }
                }
                den0 += p[0] + p[1];
                den1 += p[2] + p[3];
                sacc[n][0] = p[0]; sacc[n][1] = p[1];
                sacc[n][2] = p[2]; sacc[n][3] = p[3];
            }

            // ---- O += P V (bf16x3), P packed per k-chunk in registers ----
#pragma unroll
            for (int j = 0; j < 4; j++) {
                u32 Pah[4], Pal[4];
                {
                    float* pA = sacc[2 * j];
                    float* pB = sacc[2 * j + 1];
                    Pah[0] = cvt2(pA[1], pA[0]);
                    Pah[1] = cvt2(pA[3], pA[2]);
                    Pah[2] = cvt2(pB[1], pB[0]);
                    Pah[3] = cvt2(pB[3], pB[2]);
                    Pal[0] = cvt2(pA[1] - hi_f(Pah[0]), pA[0] - lo_f(Pah[0]));
                    Pal[1] = cvt2(pA[3] - hi_f(Pah[1]), pA[2] - lo_f(Pah[1]));
                    Pal[2] = cvt2(pB[1] - hi_f(Pah[2]), pB[0] - lo_f(Pah[2]));
                    Pal[3] = cvt2(pB[3] - hi_f(Pah[3]), pB[2] - lo_f(Pah[3]));
                }
#pragma unroll
                for (int an2 = 0; an2 < 4; an2++) {
                    u32 rh[4], rl[4];
                    u32 ad = (frow + an2 * 16) * 144 + j * 32 + koff;
                    ldsm4(rh, sVh + ad);
                    ldsm4(rl, sVl + ad);
                    u32 b0h[2] = {rh[0], rh[2]}, b1h[2] = {rh[1], rh[3]};
                    u32 b0l[2] = {rl[0], rl[2]}, b1l[2] = {rl[1], rl[3]};
                    mma16816(oacc[an2 * 2],     Pah, b0h);
                    mma16816(oacc[an2 * 2],     Pah, b0l);
                    mma16816(oacc[an2 * 2],     Pal, b0h);
                    mma16816(oacc[an2 * 2 + 1], Pah, b1h);
                    mma16816(oacc[an2 * 2 + 1], Pah, b1l);
                    mma16816(oacc[an2 * 2 + 1], Pal, b1h);
                }
            }
        }
        __syncthreads();                        // stage reusable
    }

    // ---- row-sum reduce across tg group (lanes xor 1,2) ----
    den0 += __shfl_xor_sync(0xffffffffu, den0, 1);
    den0 += __shfl_xor_sync(0xffffffffu, den0, 2);
    den1 += __shfl_xor_sync(0xffffffffu, den1, 1);
    den1 += __shfl_xor_sync(0xffffffffu, den1, 2);
    const float iv0 = __frcp_rn(den0), iv1 = __frcp_rn(den1);

    const int row0 = qbase + g;
#pragma unroll
    for (int n = 0; n < 8; n++) {
        const int col = h * 64 + n * 8 + tg * 2;
        *(float2*)&out[(size_t)(bL + row0) * 1024 + col] =
            make_float2(oacc[n][0] * iv0, oacc[n][1] * iv0);
        *(float2*)&out[(size_t)(bL + row0 + 8) * 1024 + col] =
            make_float2(oacc[n][2] * iv1, oacc[n][3] * iv1);
    }
}

// ---------------------------------------------------------------------------
extern "C" void kernel_launch(void* const* d_in, const int* in_sizes, int n_in,
                              void* d_out, int out_size)
{
    const float* x    = (const float*)d_in[0];
    const int*   mask = (const int*)  d_in[1];
    const float* Wq   = (const float*)d_in[2];
    const float* Wk   = (const float*)d_in[3];
    const float* Wv   = (const float*)d_in[4];
    float* out = (float*)d_out;

    unsigned short *wh, *wl, *xh, *xl;
    cudaGetSymbolAddress((void**)&wh, g_Wh);
    cudaGetSymbolAddress((void**)&wl, g_Wl);
    cudaGetSymbolAddress((void**)&xh, g_xh);
    cudaGetSymbolAddress((void**)&xl, g_xl);

    static int attr_set = 0;
    if (!attr_set) {
        cudaFuncSetAttribute(mm_kernel,
                             cudaFuncAttributeMaxDynamicSharedMemorySize, MM_SMEM);
        cudaFuncSetAttribute(attn_kernel,
                             cudaFuncAttributeMaxDynamicSharedMemorySize, ATT_SMEM);
        attr_set = 1;
    }

    split_kernel<<<4096, 256>>>(x,  xh, xl, 4096 * 1024 / 4);
    split_kernel<<<1024, 256>>>(Wq, wh, wl, 1024 * 1024 / 4);
    split_kernel<<<1024, 256>>>(Wk, wh + 1024 * 1024, wl + 1024 * 1024, 1024 * 1024 / 4);
    split_kernel<<<1024, 256>>>(Wv, wh + 2048 * 1024, wl + 2048 * 1024, 1024 * 1024 / 4);
    mm_kernel<<<dim3(32, 24), 256, MM_SMEM>>>();
    attn_kernel<<<dim3(16, 32), 256, ATT_SMEM>>>(mask, out);
}